// round 3
// baseline (speedup 1.0000x reference)
#include <cuda_runtime.h>
#include <cstdint>

#define BB 16
#define NN 4096
#define CPTS 64
#define MM 1024
#define KK 32
#define NSAMP (BB*MM*KK)          // 524288
#define RADIUS 0.2f
#define EPS 1e-5f

typedef unsigned long long u64;

// ---------------- scratch (device globals; no allocation allowed) -------------
__device__ float g_newxyz[BB*MM*3];
__device__ int   g_idx[BB*MM*KK];
__device__ float g_h1[(size_t)NSAMP*64];
__device__ float g_h2[(size_t)NSAMP*64];
__device__ float g_h3[(size_t)NSAMP*128];
__device__ float g_sums[3][256];   // per layer: sum[c] at [c], sumsq at [128+c]
__device__ float g_aff[3][256];    // per layer: a[c] at [c],   bias at [128+c]

// exact-order helpers (match XLA: mul then add, no fma contraction)
__device__ __forceinline__ float sq3(float x, float y, float z){
    return __fadd_rn(__fadd_rn(__fmul_rn(x,x),__fmul_rn(y,y)),__fmul_rn(z,z));
}
__device__ __forceinline__ float dot3(float ax,float ay,float az,float bx,float by,float bz){
    return __fadd_rn(__fadd_rn(__fmul_rn(ax,bx),__fmul_rn(ay,by)),__fmul_rn(az,bz));
}

// ---------------- packed f32x2 helpers (SASS FFMA2 — PTX-only path) -----------
__device__ __forceinline__ u64 ffma2(u64 a, u64 b, u64 c){
    u64 d; asm("fma.rn.f32x2 %0, %1, %2, %3;" : "=l"(d) : "l"(a), "l"(b), "l"(c)); return d;
}
__device__ __forceinline__ u64 fadd2(u64 a, u64 b){
    u64 d; asm("add.rn.f32x2 %0, %1, %2;" : "=l"(d) : "l"(a), "l"(b)); return d;
}
__device__ __forceinline__ u64 fmul2(u64 a, u64 b){
    u64 d; asm("mul.rn.f32x2 %0, %1, %2;" : "=l"(d) : "l"(a), "l"(b)); return d;
}
__device__ __forceinline__ u64 pack2(float x){
    u64 d; asm("mov.b64 %0, {%1, %1};" : "=l"(d) : "f"(x)); return d;
}
__device__ __forceinline__ float lo2(u64 v){ return __uint_as_float((unsigned)(v & 0xffffffffu)); }
__device__ __forceinline__ float hi2(u64 v){ return __uint_as_float((unsigned)(v >> 32)); }

// ---------------- zero stats ----------------
__global__ void zero_stats_kernel(){
    int t = threadIdx.x;
    float* p = &g_sums[0][0];
    for(int i=t;i<3*256;i+=256) p[i]=0.f;
}

// ---------------- FPS: one block per batch, points in registers ---------------
__global__ void __launch_bounds__(1024) fps_kernel(const float* __restrict__ xyz,
                                                   float* __restrict__ out_xyz){
    int b = blockIdx.x;
    const float* X = xyz + b*NN*3;
    int t = threadIdx.x;
    int lane = t & 31, wid = t >> 5;

    float px[4],py[4],pz[4],md[4];
#pragma unroll
    for(int j=0;j<4;j++){
        int i = t + j*1024;
        px[j]=X[i*3]; py[j]=X[i*3+1]; pz[j]=X[i*3+2];
        md[j]=1e10f;
    }

    __shared__ float s_val[32];
    __shared__ int   s_idx[32];
    __shared__ float s_c[3];

    int far = 0;   // meaningful on thread 0 only
    for(int m=0;m<MM;m++){
        if(t==0){
            float cx=X[far*3], cy=X[far*3+1], cz=X[far*3+2];
            s_c[0]=cx; s_c[1]=cy; s_c[2]=cz;
            int o = b*MM + m;
            g_newxyz[o*3]=cx; g_newxyz[o*3+1]=cy; g_newxyz[o*3+2]=cz;
            out_xyz[o*3]=cx;  out_xyz[o*3+1]=cy;  out_xyz[o*3+2]=cz;
        }
        __syncthreads();
        float cx=s_c[0], cy=s_c[1], cz=s_c[2];

        float best=-1.f; int bi=0;
#pragma unroll
        for(int j=0;j<4;j++){
            float dx=px[j]-cx, dy=py[j]-cy, dz=pz[j]-cz;
            float d = sq3(dx,dy,dz);
            float nd = fminf(md[j], d);
            md[j] = nd;
            if(nd > best){ best = nd; bi = t + j*1024; }   // strict > keeps lowest idx
        }
        // warp-level argmax (first-index tie break)
#pragma unroll
        for(int off=16; off>0; off>>=1){
            float v  = __shfl_down_sync(0xffffffffu, best, off);
            int   ii = __shfl_down_sync(0xffffffffu, bi,   off);
            if(v > best || (v == best && ii < bi)){ best = v; bi = ii; }
        }
        if(lane==0){ s_val[wid]=best; s_idx[wid]=bi; }
        __syncthreads();
        if(wid==0){
            best = s_val[lane]; bi = s_idx[lane];
#pragma unroll
            for(int off=16; off>0; off>>=1){
                float v  = __shfl_down_sync(0xffffffffu, best, off);
                int   ii = __shfl_down_sync(0xffffffffu, bi,   off);
                if(v > best || (v == best && ii < bi)){ best = v; bi = ii; }
            }
            if(t==0) far = bi;
        }
    }
}

// ---------------- ball query: one warp per center, early exit -----------------
__global__ void __launch_bounds__(256) ballq_kernel(const float* __restrict__ xyz,
                                                    float* __restrict__ out_idx_f){
    int gw = (blockIdx.x * blockDim.x + threadIdx.x) >> 5;   // center id
    int lane = threadIdx.x & 31;
    int wl = threadIdx.x >> 5;
    __shared__ int s_list[8][KK];
    if(gw >= BB*MM) return;
    int b = gw >> 10;
    const float* X = xyz + b*NN*3;
    float cx=g_newxyz[gw*3], cy=g_newxyz[gw*3+1], cz=g_newxyz[gw*3+2];
    float cn = sq3(cx,cy,cz);

    int filled = 0;
    for(int base=0; base<NN; base+=32){
        int i = base + lane;
        float x=X[i*3], y=X[i*3+1], z=X[i*3+2];
        float pn  = sq3(x,y,z);
        float dt  = dot3(cx,cy,cz,x,y,z);
        float d2  = __fadd_rn(cn,pn) - 2.0f*dt;
        float d   = sqrtf(fmaxf(d2, 0.f));
        bool ok   = !(d > RADIUS);
        unsigned msk = __ballot_sync(0xffffffffu, ok);
        int pos = filled + __popc(msk & ((1u<<lane)-1u));
        if(ok && pos < KK) s_list[wl][pos] = i;
        filled += __popc(msk);
        if(filled >= KK) break;
    }
    __syncwarp();
    int cnt = filled < KK ? filled : KK;
    int first = s_list[wl][0];          // always >=1 member (center itself)
    int v = (lane < cnt) ? s_list[wl][lane] : first;
    g_idx[gw*KK + lane] = v;
    out_idx_f[gw*KK + lane] = (float)v;
}

// ---------------- fused gather/affine + GEMM (f32x2) + fused stats ------------
// LAYER 0: gather feats (points cols 0..63, xyz-diff cols 64..66; W permuted)
// LAYER 1/2: input = relu(a*h_prev + c) applied on smem load
template<int CIN, int COUT, int LAYER>
__global__ void __launch_bounds__(256) mlp_kernel(const float* __restrict__ xyz,
                                                  const float* __restrict__ points,
                                                  const float* __restrict__ W){
    extern __shared__ float smem[];
    float* Fs = smem;                 // [128][68]
    float* Ws = smem + 128*68;        // [CIN][COUT]
    int tid = threadIdx.x;
    int tile = blockIdx.x * 128;

    // load (and permute/transpose) W into [c][o]
    for(int e = tid; e < CIN*COUT; e += 256){
        int c = e / COUT, o = e - c*COUT;
        int src = (LAYER==0) ? ((c < 64) ? (c+3) : (c-64)) : c;
        Ws[c*COUT + o] = W[o*CIN + src];
    }

    // load F tile: 2 threads per sample
    int r = tid >> 1, half = tid & 1;
    int s = tile + r;
    if(LAYER == 0){
        int m_ = (s >> 5) & (MM-1);
        int b_ = s >> 15;
        int idx = g_idx[s];
        const float* prow = points + ((size_t)(b_*NN + idx))*CPTS + half*32;
#pragma unroll
        for(int q=0;q<8;q++)
            *(float4*)&Fs[r*68 + half*32 + q*4] = *(const float4*)(prow + q*4);
        if(half==0){
            int cm = b_*MM + m_;
            const float* xp = xyz + (size_t)(b_*NN + idx)*3;
            Fs[r*68+64] = xp[0] - g_newxyz[cm*3];
            Fs[r*68+65] = xp[1] - g_newxyz[cm*3+1];
            Fs[r*68+66] = xp[2] - g_newxyz[cm*3+2];
        }
    } else {
        const float* hin = (LAYER==1) ? g_h1 : g_h2;
        const float* aff = g_aff[LAYER-1];
        const float* hrow = hin + (size_t)s*64 + half*32;
#pragma unroll
        for(int q=0;q<8;q++){
            int cb = half*32 + q*4;
            float4 v  = *(const float4*)(hrow + q*4);
            float4 av = *(const float4*)&aff[cb];
            float4 cv = *(const float4*)&aff[128+cb];
            v.x = fmaxf(v.x*av.x+cv.x, 0.f);
            v.y = fmaxf(v.y*av.y+cv.y, 0.f);
            v.z = fmaxf(v.z*av.z+cv.z, 0.f);
            v.w = fmaxf(v.w*av.w+cv.w, 0.f);
            *(float4*)&Fs[r*68 + cb] = v;
        }
    }
    __syncthreads();

    float* hout = (LAYER==0) ? g_h1 : (LAYER==1) ? g_h2 : g_h3;
    float* sums = g_sums[LAYER];
    int og = tid & 7, sg = tid >> 3;
    const int OC = (COUT > 64) ? 2 : 1;
#pragma unroll
    for(int oc=0; oc<OC; oc++){
        // 4 samples x 4 packed pairs (= 8 output channels)
        u64 acc2[4][4];
#pragma unroll
        for(int i=0;i<4;i++)
#pragma unroll
            for(int p=0;p<4;p++) acc2[i][p]=0ull;
        int obase = oc*64 + og*8;
#pragma unroll 4
        for(int c=0;c<CIN;c++){
            ulonglong2 wa = *(const ulonglong2*)&Ws[c*COUT + obase];     // pairs 0,1
            ulonglong2 wb = *(const ulonglong2*)&Ws[c*COUT + obase + 4]; // pairs 2,3
#pragma unroll
            for(int i=0;i<4;i++){
                u64 ff = pack2(Fs[(sg*4+i)*68 + c]);
                acc2[i][0] = ffma2(ff, wa.x, acc2[i][0]);
                acc2[i][1] = ffma2(ff, wa.y, acc2[i][1]);
                acc2[i][2] = ffma2(ff, wb.x, acc2[i][2]);
                acc2[i][3] = ffma2(ff, wb.y, acc2[i][3]);
            }
        }
        // store h
#pragma unroll
        for(int i=0;i<4;i++){
            size_t so = (size_t)(tile + sg*4 + i)*COUT + obase;
            *(ulonglong2*)&hout[so]   = make_ulonglong2(acc2[i][0], acc2[i][1]);
            *(ulonglong2*)&hout[so+4] = make_ulonglong2(acc2[i][2], acc2[i][3]);
        }
        // fused per-channel stats: per-thread over 4 samples, packed
        u64 sum2[4], ssq2[4];
#pragma unroll
        for(int p=0;p<4;p++){
            sum2[p] = fadd2(fadd2(acc2[0][p],acc2[1][p]), fadd2(acc2[2][p],acc2[3][p]));
            ssq2[p] = ffma2(acc2[0][p],acc2[0][p],
                       ffma2(acc2[1][p],acc2[1][p],
                        ffma2(acc2[2][p],acc2[2][p],
                         fmul2(acc2[3][p],acc2[3][p]))));
        }
        // reduce across the 4 lanes sharing this og (lanes og, og+8, og+16, og+24)
#pragma unroll
        for(int p=0;p<4;p++){
            sum2[p] = fadd2(sum2[p], __shfl_xor_sync(0xffffffffu, sum2[p], 8));
            sum2[p] = fadd2(sum2[p], __shfl_xor_sync(0xffffffffu, sum2[p], 16));
            ssq2[p] = fadd2(ssq2[p], __shfl_xor_sync(0xffffffffu, ssq2[p], 8));
            ssq2[p] = fadd2(ssq2[p], __shfl_xor_sync(0xffffffffu, ssq2[p], 16));
        }
        if((tid & 31) < 8){
#pragma unroll
            for(int p=0;p<4;p++){
                int c0 = obase + 2*p;
                atomicAdd(&sums[c0],       lo2(sum2[p]));
                atomicAdd(&sums[c0+1],     hi2(sum2[p]));
                atomicAdd(&sums[128+c0],   lo2(ssq2[p]));
                atomicAdd(&sums[128+c0+1], hi2(ssq2[p]));
            }
        }
    }
}

// ---------------- fold norm into affine ---------------------------------------
__global__ void affine_kernel(int layer, int CH, const float* __restrict__ g,
                              const float* __restrict__ b){
    int c = threadIdx.x;
    if(c < CH){
        const float* sums = g_sums[layer];
        const float inv = 1.f/(float)NSAMP;     // 2^-19 exact
        float mean = sums[c]*inv;
        float var  = sums[128+c]*inv - mean*mean;
        float a = g[c]*rsqrtf(var + EPS);
        g_aff[layer][c]     = a;
        g_aff[layer][128+c] = b[c] - mean*a;
    }
}

// ---------------- final relu + max over K -------------------------------------
__global__ void __launch_bounds__(128) maxpool_kernel(float* __restrict__ outp){
    int bm = blockIdx.x, o = threadIdx.x;
    float a = g_aff[2][o], cb = g_aff[2][128+o];
    const float* base = g_h3 + (size_t)bm*KK*128 + o;
    float best = 0.f;
#pragma unroll
    for(int k=0;k<KK;k++)
        best = fmaxf(best, fmaxf(a*base[k*128]+cb, 0.f));
    outp[(size_t)bm*128 + o] = best;
}

// ---------------- launcher ----------------------------------------------------
extern "C" void kernel_launch(void* const* d_in, const int* in_sizes, int n_in,
                              void* d_out, int out_size){
    const float* xyz    = (const float*)d_in[0];
    const float* points = (const float*)d_in[1];
    const float* W0 = (const float*)d_in[2];
    const float* g0 = (const float*)d_in[3];
    const float* b0 = (const float*)d_in[4];
    const float* W1 = (const float*)d_in[5];
    const float* g1 = (const float*)d_in[6];
    const float* b1 = (const float*)d_in[7];
    const float* W2 = (const float*)d_in[8];
    const float* g2 = (const float*)d_in[9];
    const float* b2 = (const float*)d_in[10];

    float* out      = (float*)d_out;
    float* out_xyz  = out;                              // (B,M,3)
    float* out_pts  = out + BB*MM*3;                    // (B,M,128)
    float* out_idxf = out + BB*MM*3 + BB*MM*128;        // (B,M,K) as float

    const int SM1 = (128*68 + 67*64)*4;    // 51968
    const int SM2 = (128*68 + 64*64)*4;    // 51200
    const int SM3 = (128*68 + 64*128)*4;   // 67584
    cudaFuncSetAttribute(mlp_kernel<67,64,0>,  cudaFuncAttributeMaxDynamicSharedMemorySize, SM1);
    cudaFuncSetAttribute(mlp_kernel<64,64,1>,  cudaFuncAttributeMaxDynamicSharedMemorySize, SM2);
    cudaFuncSetAttribute(mlp_kernel<64,128,2>, cudaFuncAttributeMaxDynamicSharedMemorySize, SM3);

    zero_stats_kernel<<<1,256>>>();
    fps_kernel<<<BB,1024>>>(xyz, out_xyz);
    ballq_kernel<<<(BB*MM)/8, 256>>>(xyz, out_idxf);

    mlp_kernel<67,64,0><<<NSAMP/128, 256, SM1>>>(xyz, points, W0);
    affine_kernel<<<1,128>>>(0, 64, g0, b0);

    mlp_kernel<64,64,1><<<NSAMP/128, 256, SM2>>>(xyz, points, W1);
    affine_kernel<<<1,128>>>(1, 64, g1, b1);

    mlp_kernel<64,128,2><<<NSAMP/128, 256, SM3>>>(xyz, points, W2);
    affine_kernel<<<1,128>>>(2, 128, g2, b2);

    maxpool_kernel<<<BB*MM,128>>>(out_pts);
    (void)in_sizes; (void)n_in; (void)out_size;
}

// round 4
// speedup vs baseline: 1.0794x; 1.0794x over previous
#include <cuda_runtime.h>
#include <cstdint>

#define BB 16
#define NN 4096
#define CPTS 64
#define MM 1024
#define KK 32
#define NSAMP (BB*MM*KK)          // 524288
#define RADIUS 0.2f
#define EPS 1e-5f

typedef unsigned long long u64;

// ---------------- scratch (device globals; no allocation allowed) -------------
__device__ float g_newxyz[BB*MM*3];
__device__ int   g_idx[BB*MM*KK];
__device__ float g_h1[(size_t)NSAMP*64];
__device__ float g_h2[(size_t)NSAMP*64];
__device__ float g_h3[(size_t)NSAMP*128];
__device__ float g_sums[3][256];   // per layer: sum[c] at [c], sumsq at [128+c]
__device__ float g_aff[3][256];    // per layer: a[c] at [c],   bias at [128+c]

// exact-order helpers (match XLA: mul then add, no fma contraction)
__device__ __forceinline__ float sq3(float x, float y, float z){
    return __fadd_rn(__fadd_rn(__fmul_rn(x,x),__fmul_rn(y,y)),__fmul_rn(z,z));
}
__device__ __forceinline__ float dot3(float ax,float ay,float az,float bx,float by,float bz){
    return __fadd_rn(__fadd_rn(__fmul_rn(ax,bx),__fmul_rn(ay,by)),__fmul_rn(az,bz));
}

// ---------------- packed f32x2 helpers (SASS FFMA2 — PTX-only path) -----------
__device__ __forceinline__ u64 ffma2(u64 a, u64 b, u64 c){
    u64 d; asm("fma.rn.f32x2 %0, %1, %2, %3;" : "=l"(d) : "l"(a), "l"(b), "l"(c)); return d;
}
__device__ __forceinline__ u64 fadd2(u64 a, u64 b){
    u64 d; asm("add.rn.f32x2 %0, %1, %2;" : "=l"(d) : "l"(a), "l"(b)); return d;
}
__device__ __forceinline__ u64 fmul2(u64 a, u64 b){
    u64 d; asm("mul.rn.f32x2 %0, %1, %2;" : "=l"(d) : "l"(a), "l"(b)); return d;
}
__device__ __forceinline__ u64 pack2(float x){
    u64 d; asm("mov.b64 %0, {%1, %1};" : "=l"(d) : "f"(x)); return d;
}
__device__ __forceinline__ float lo2(u64 v){ return __uint_as_float((unsigned)(v & 0xffffffffu)); }
__device__ __forceinline__ float hi2(u64 v){ return __uint_as_float((unsigned)(v >> 32)); }
__device__ __forceinline__ u64 umax64(u64 a, u64 b){ return a > b ? a : b; }

// ---------------- FPS: 256 threads, 1 barrier/iter, u64 argmax keys -----------
__global__ void __launch_bounds__(256) fps_kernel(const float* __restrict__ xyz,
                                                  float* __restrict__ out_xyz){
    extern __shared__ float sm[];
    float* sx = sm;              // [NN]
    float* sy = sm + NN;
    float* sz = sm + 2*NN;
    int*   s_ind  = (int*)(sm + 3*NN);          // [MM]
    u64*   s_part = (u64*)(s_ind + MM);         // [2][8] double-buffered

    int b = blockIdx.x;
    const float* X = xyz + b*NN*3;
    int t = threadIdx.x, lane = t & 31, w = t >> 5;

    if(b == 0){   // fold former zero_stats kernel
        for(int i = t; i < 3*256; i += 256) (&g_sums[0][0])[i] = 0.f;
    }

    float px[16], py[16], pz[16], md[16];
#pragma unroll
    for(int j = 0; j < 16; j++){
        int i = t + j*256;
        float x = X[i*3], y = X[i*3+1], z = X[i*3+2];
        px[j] = x; py[j] = y; pz[j] = z; md[j] = 1e10f;
        sx[i] = x; sy[i] = y; sz[i] = z;
    }
    __syncthreads();

    int far = 0;   // all threads track it redundantly
    for(int m = 0; m < MM; m++){
        if(t == 0) s_ind[m] = far;
        float cx = sx[far], cy = sy[far], cz = sz[far];

        float best = -1.f; int bj = 0;
#pragma unroll
        for(int j = 0; j < 16; j++){
            float dx = px[j]-cx, dy = py[j]-cy, dz = pz[j]-cz;
            float d  = sq3(dx,dy,dz);
            float nd = fminf(md[j], d);
            md[j] = nd;
            if(nd > best){ best = nd; bj = j; }   // strict >: lowest idx on tie
        }
        u64 key = ((u64)__float_as_uint(best) << 32)
                | (unsigned)((NN-1) - (t + bj*256));
#pragma unroll
        for(int off = 16; off > 0; off >>= 1)
            key = umax64(key, __shfl_down_sync(0xffffffffu, key, off));

        u64* P = s_part + (m & 1)*8;
        if(lane == 0) P[w] = key;
        __syncthreads();
        // tree max over 8 partials (every thread, no 2nd barrier needed:
        // next iter writes the other buffer)
        u64 a0 = umax64(P[0], P[1]);
        u64 a1 = umax64(P[2], P[3]);
        u64 a2 = umax64(P[4], P[5]);
        u64 a3 = umax64(P[6], P[7]);
        u64 kk = umax64(umax64(a0,a1), umax64(a2,a3));
        far = (NN-1) - (int)(kk & 0xFFFFu);
    }
    __syncthreads();

    for(int m = t; m < MM; m += 256){
        int id = s_ind[m];
        int o = b*MM + m;
        float x = sx[id], y = sy[id], z = sz[id];
        g_newxyz[o*3] = x; g_newxyz[o*3+1] = y; g_newxyz[o*3+2] = z;
        out_xyz[o*3]  = x; out_xyz[o*3+1]  = y; out_xyz[o*3+2]  = z;
    }
}

// ---------------- ball query: one warp per center, early exit -----------------
__global__ void __launch_bounds__(256) ballq_kernel(const float* __restrict__ xyz,
                                                    float* __restrict__ out_idx_f){
    int gw = (blockIdx.x * blockDim.x + threadIdx.x) >> 5;   // center id
    int lane = threadIdx.x & 31;
    int wl = threadIdx.x >> 5;
    __shared__ int s_list[8][KK];
    if(gw >= BB*MM) return;
    int b = gw >> 10;
    const float* X = xyz + b*NN*3;
    float cx=g_newxyz[gw*3], cy=g_newxyz[gw*3+1], cz=g_newxyz[gw*3+2];
    float cn = sq3(cx,cy,cz);

    int filled = 0;
    for(int base=0; base<NN; base+=32){
        int i = base + lane;
        float x=X[i*3], y=X[i*3+1], z=X[i*3+2];
        float pn  = sq3(x,y,z);
        float dt  = dot3(cx,cy,cz,x,y,z);
        float d2  = __fadd_rn(cn,pn) - 2.0f*dt;
        float d   = sqrtf(fmaxf(d2, 0.f));
        bool ok   = !(d > RADIUS);
        unsigned msk = __ballot_sync(0xffffffffu, ok);
        int pos = filled + __popc(msk & ((1u<<lane)-1u));
        if(ok && pos < KK) s_list[wl][pos] = i;
        filled += __popc(msk);
        if(filled >= KK) break;
    }
    __syncwarp();
    int cnt = filled < KK ? filled : KK;
    int first = s_list[wl][0];          // always >=1 member (center itself)
    int v = (lane < cnt) ? s_list[wl][lane] : first;
    g_idx[gw*KK + lane] = v;
    out_idx_f[gw*KK + lane] = (float)v;
}

// ---------------- fused gather/affine + GEMM (f32x2) + fused stats ------------
// WSS = padded smem stride for Ws (>=COUT, 16B-aligned, 4-bank offset)
template<int CIN, int COUT, int LAYER, int WSS>
__global__ void __launch_bounds__(256) mlp_kernel(const float* __restrict__ xyz,
                                                  const float* __restrict__ points,
                                                  const float* __restrict__ W){
    extern __shared__ float smem[];
    float* Fs = smem;                 // [128][68]
    float* Ws = smem + 128*68;        // [CIN][WSS]
    int tid = threadIdx.x;
    int tile = blockIdx.x * 128;

    // coalesced W read, transposed (+permuted) store
    for(int e = tid; e < CIN*COUT; e += 256){
        int o = e / CIN, src = e - o*CIN;
        int c = (LAYER==0) ? ((src < 3) ? (64+src) : (src-3)) : src;
        Ws[c*WSS + o] = W[e];
    }

    if(LAYER == 0){
        // gather: 2 threads per sample
        int r = tid >> 1, half = tid & 1;
        int s = tile + r;
        int m_ = (s >> 5) & (MM-1);
        int b_ = s >> 15;
        int idx = g_idx[s];
        const float* prow = points + ((size_t)(b_*NN + idx))*CPTS + half*32;
#pragma unroll
        for(int q=0;q<8;q++)
            *(float4*)&Fs[r*68 + half*32 + q*4] = *(const float4*)(prow + q*4);
        if(half==0){
            int cm = b_*MM + m_;
            const float* xp = xyz + (size_t)(b_*NN + idx)*3;
            Fs[r*68+64] = xp[0] - g_newxyz[cm*3];
            Fs[r*68+65] = xp[1] - g_newxyz[cm*3+1];
            Fs[r*68+66] = xp[2] - g_newxyz[cm*3+2];
        }
    } else {
        // linear coalesced load of the h tile + affine+relu
        const float* hin = (LAYER==1) ? g_h1 : g_h2;
        const float* aff = g_aff[LAYER-1];
        int ch0 = (tid & 15) * 4;                      // constant per thread
        float4 av = *(const float4*)&aff[ch0];
        float4 cv = *(const float4*)&aff[128+ch0];
        const float4* src4 = (const float4*)(hin + (size_t)tile*64);
        for(int k = tid; k < 128*16; k += 256){
            float4 v = src4[k];
            int sample = k >> 4;                       // k&15 == tid&15
            v.x = fmaxf(v.x*av.x+cv.x, 0.f);
            v.y = fmaxf(v.y*av.y+cv.y, 0.f);
            v.z = fmaxf(v.z*av.z+cv.z, 0.f);
            v.w = fmaxf(v.w*av.w+cv.w, 0.f);
            *(float4*)&Fs[sample*68 + ch0] = v;
        }
    }
    __syncthreads();

    float* hout = (LAYER==0) ? g_h1 : (LAYER==1) ? g_h2 : g_h3;
    float* sums = g_sums[LAYER];
    int og = tid & 7, sg = tid >> 3;
    const int OC = (COUT > 64) ? 2 : 1;
#pragma unroll
    for(int oc=0; oc<OC; oc++){
        // 4 samples x 4 packed pairs (= 8 output channels)
        u64 acc2[4][4];
#pragma unroll
        for(int i=0;i<4;i++)
#pragma unroll
            for(int p=0;p<4;p++) acc2[i][p]=0ull;
        int obase = oc*64 + og*8;
#pragma unroll 4
        for(int c=0;c<CIN;c++){
            ulonglong2 wa = *(const ulonglong2*)&Ws[c*WSS + obase];     // pairs 0,1
            ulonglong2 wb = *(const ulonglong2*)&Ws[c*WSS + obase + 4]; // pairs 2,3
#pragma unroll
            for(int i=0;i<4;i++){
                u64 ff = pack2(Fs[(sg*4+i)*68 + c]);
                acc2[i][0] = ffma2(ff, wa.x, acc2[i][0]);
                acc2[i][1] = ffma2(ff, wa.y, acc2[i][1]);
                acc2[i][2] = ffma2(ff, wb.x, acc2[i][2]);
                acc2[i][3] = ffma2(ff, wb.y, acc2[i][3]);
            }
        }
        // store h
#pragma unroll
        for(int i=0;i<4;i++){
            size_t so = (size_t)(tile + sg*4 + i)*COUT + obase;
            *(ulonglong2*)&hout[so]   = make_ulonglong2(acc2[i][0], acc2[i][1]);
            *(ulonglong2*)&hout[so+4] = make_ulonglong2(acc2[i][2], acc2[i][3]);
        }
        // fused per-channel stats: per-thread over 4 samples, packed
        u64 sum2[4], ssq2[4];
#pragma unroll
        for(int p=0;p<4;p++){
            sum2[p] = fadd2(fadd2(acc2[0][p],acc2[1][p]), fadd2(acc2[2][p],acc2[3][p]));
            ssq2[p] = ffma2(acc2[0][p],acc2[0][p],
                       ffma2(acc2[1][p],acc2[1][p],
                        ffma2(acc2[2][p],acc2[2][p],
                         fmul2(acc2[3][p],acc2[3][p]))));
        }
        // reduce across the 4 lanes sharing this og (lanes og, og+8, og+16, og+24)
#pragma unroll
        for(int p=0;p<4;p++){
            sum2[p] = fadd2(sum2[p], __shfl_xor_sync(0xffffffffu, sum2[p], 8));
            sum2[p] = fadd2(sum2[p], __shfl_xor_sync(0xffffffffu, sum2[p], 16));
            ssq2[p] = fadd2(ssq2[p], __shfl_xor_sync(0xffffffffu, ssq2[p], 8));
            ssq2[p] = fadd2(ssq2[p], __shfl_xor_sync(0xffffffffu, ssq2[p], 16));
        }
        if((tid & 31) < 8){
#pragma unroll
            for(int p=0;p<4;p++){
                int c0 = obase + 2*p;
                atomicAdd(&sums[c0],       lo2(sum2[p]));
                atomicAdd(&sums[c0+1],     hi2(sum2[p]));
                atomicAdd(&sums[128+c0],   lo2(ssq2[p]));
                atomicAdd(&sums[128+c0+1], hi2(ssq2[p]));
            }
        }
    }
}

// ---------------- fold norm into affine ---------------------------------------
__global__ void affine_kernel(int layer, int CH, const float* __restrict__ g,
                              const float* __restrict__ b){
    int c = threadIdx.x;
    if(c < CH){
        const float* sums = g_sums[layer];
        const float inv = 1.f/(float)NSAMP;     // 2^-19 exact
        float mean = sums[c]*inv;
        float var  = sums[128+c]*inv - mean*mean;
        float a = g[c]*rsqrtf(var + EPS);
        g_aff[layer][c]     = a;
        g_aff[layer][128+c] = b[c] - mean*a;
    }
}

// ---------------- final relu + max over K -------------------------------------
__global__ void __launch_bounds__(128) maxpool_kernel(float* __restrict__ outp){
    int bm = blockIdx.x, o = threadIdx.x;
    float a = g_aff[2][o], cb = g_aff[2][128+o];
    const float* base = g_h3 + (size_t)bm*KK*128 + o;
    float best = 0.f;
#pragma unroll
    for(int k=0;k<KK;k++)
        best = fmaxf(best, fmaxf(a*base[k*128]+cb, 0.f));
    outp[(size_t)bm*128 + o] = best;
}

// ---------------- launcher ----------------------------------------------------
extern "C" void kernel_launch(void* const* d_in, const int* in_sizes, int n_in,
                              void* d_out, int out_size){
    const float* xyz    = (const float*)d_in[0];
    const float* points = (const float*)d_in[1];
    const float* W0 = (const float*)d_in[2];
    const float* g0 = (const float*)d_in[3];
    const float* b0 = (const float*)d_in[4];
    const float* W1 = (const float*)d_in[5];
    const float* g1 = (const float*)d_in[6];
    const float* b1 = (const float*)d_in[7];
    const float* W2 = (const float*)d_in[8];
    const float* g2 = (const float*)d_in[9];
    const float* b2 = (const float*)d_in[10];

    float* out      = (float*)d_out;
    float* out_xyz  = out;                              // (B,M,3)
    float* out_pts  = out + BB*MM*3;                    // (B,M,128)
    float* out_idxf = out + BB*MM*3 + BB*MM*128;        // (B,M,K) as float

    const int FPS_SM = (3*NN + MM)*4 + 16*8;            // 53376
    const int SM1 = (128*68 + 67*68)*4;                 // 53040
    const int SM2 = (128*68 + 64*68)*4;                 // 52224
    const int SM3 = (128*68 + 64*132)*4;                // 68608
    cudaFuncSetAttribute(fps_kernel, cudaFuncAttributeMaxDynamicSharedMemorySize, FPS_SM);
    cudaFuncSetAttribute(mlp_kernel<67,64,0,68>,   cudaFuncAttributeMaxDynamicSharedMemorySize, SM1);
    cudaFuncSetAttribute(mlp_kernel<64,64,1,68>,   cudaFuncAttributeMaxDynamicSharedMemorySize, SM2);
    cudaFuncSetAttribute(mlp_kernel<64,128,2,132>, cudaFuncAttributeMaxDynamicSharedMemorySize, SM3);

    fps_kernel<<<BB,256,FPS_SM>>>(xyz, out_xyz);
    ballq_kernel<<<(BB*MM)/8, 256>>>(xyz, out_idxf);

    mlp_kernel<67,64,0,68><<<NSAMP/128, 256, SM1>>>(xyz, points, W0);
    affine_kernel<<<1,128>>>(0, 64, g0, b0);

    mlp_kernel<64,64,1,68><<<NSAMP/128, 256, SM2>>>(xyz, points, W1);
    affine_kernel<<<1,128>>>(1, 64, g1, b1);

    mlp_kernel<64,128,2,132><<<NSAMP/128, 256, SM3>>>(xyz, points, W2);
    affine_kernel<<<1,128>>>(2, 128, g2, b2);

    maxpool_kernel<<<BB*MM,128>>>(out_pts);
    (void)in_sizes; (void)n_in; (void)out_size;
}